// round 13
// baseline (speedup 1.0000x reference)
#include <cuda_runtime.h>
#include <cuda_fp16.h>

#define HH 224
#define WW 224
#define BB 4
#define SS 21
#define RR 5
#define HW (HH*WW)

#define TILE 32
#define TPB 256
#define IN_DIM 48
#define PITCH 49          // 48 + 1 pad (8B entries): spreads banks across rows

// Stage-1 intermediate: 84 shifted images, HWC pixels packed as half4 (8 B).
__device__ uint2 g_x1[SS * BB * HW];    // 33.7 MB

// cos/sin of ANGLES = {-0.5236, -0.2618, 0, 0.2618, 0.5236} (float64-accurate)
__constant__ float c_cos[RR] = {0.86602479158f, 0.96592566784f, 1.0f,
                                0.96592566784f, 0.86602479158f};
__constant__ float c_sin[RR] = {-0.50000106036f, -0.25881963644f, 0.0f,
                                 0.25881963644f,  0.50000106036f};

// ---------------------------------------------------------------------------
// Stage 1: axis-aligned shifts are exactly 2-tap (frac is 0 or 0.5, one axis).
// One thread = one pixel. Writes 8B half4.
// ---------------------------------------------------------------------------
__global__ void __launch_bounds__(256) stage1_shift(const float* __restrict__ xs)
{
    int idx = blockIdx.x * 256 + threadIdx.x;
    if (idx >= HW) return;
    int n = blockIdx.y;          // 0..83 = s*B + b
    int s = n >> 2;
    int b = n & 3;
    int h = idx / WW;
    int w = idx - h * WW;

    // Shift order: up p=1..5 (+y), down p=1..5 (-y), left (+x), right (-x),
    // plus identity. Normalized p/(W-1) -> p/2 pixels.
    int axis;                    // 0 = shift along y, 1 = along x
    float delta;
    if      (s < 5)  { axis = 0; delta =  (float)(s + 1)  * 0.5f; }
    else if (s < 10) { axis = 0; delta = -(float)(s - 4)  * 0.5f; }
    else if (s < 15) { axis = 1; delta =  (float)(s - 9)  * 0.5f; }
    else if (s < 20) { axis = 1; delta = -(float)(s - 14) * 0.5f; }
    else             { axis = 0; delta = 0.f; }

    float coord = (axis == 0 ? (float)h : (float)w) + delta;
    float i0f = floorf(coord);
    int   i0  = (int)i0f;
    float f   = coord - i0f;     // 0 or 0.5

    const float* img = xs + b * (HW * 3);
    float ax = 0.f, ay = 0.f, az = 0.f;
    #pragma unroll
    for (int j = 0; j < 2; j++) {
        int i = i0 + j;
        float wt = j ? f : (1.f - f);
        int y = axis == 0 ? i : h;
        int x = axis == 0 ? w : i;
        if (wt != 0.f && (unsigned)y < HH && (unsigned)x < WW) {
            const float* p = img + (y * WW + x) * 3;
            ax += wt * p[0];
            ay += wt * p[1];
            az += wt * p[2];
        }
    }
    __half2 lo = __floats2half2_rn(ax, ay);
    __half2 hi = __floats2half2_rn(az, 0.f);
    uint2 v;
    v.x = *(unsigned*)&lo;
    v.y = *(unsigned*)&hi;
    g_x1[n * HW + idx] = v;
}

// ---------------------------------------------------------------------------
// Stage 2: rotation sampling, smem-tiled (R8 layout: 8B cells, 4x LDS.64).
// Out-of-image cells are ZERO-filled in the tile, which implements the
// zero-padding exactly: the inner loop has NO boundary logic at all.
// Every tap is provably inside the 48x48 tile (span <= 46).
// Thread = 4 horizontally-consecutive pixels -> 3 STG.128.
// ---------------------------------------------------------------------------
__global__ void __launch_bounds__(TPB) stage2_rotate(float* __restrict__ out)
{
    __shared__ uint2 tile[IN_DIM * PITCH];

    int m = blockIdx.y;                        // 0..419
    int r = m / (SS * BB);
    int n = m - r * (SS * BB);
    int tbx = blockIdx.x % (WW / TILE);
    int tby = blockIdx.x / (WW / TILE);
    int tx = tbx * TILE;
    int ty = tby * TILE;

    const float cx = 111.5f;
    float cs = c_cos[r], sn = c_sin[r];

    // Input bounding box of the tile (linear map -> extrema at corners).
    float u0 = (float)tx - cx,  u1 = (float)(tx + TILE - 1) - cx;
    float v0 = (float)ty - cx,  v1 = (float)(ty + TILE - 1) - cx;
    float ix00 = u0*cs + v0*sn, ix01 = u0*cs + v1*sn;
    float ix10 = u1*cs + v0*sn, ix11 = u1*cs + v1*sn;
    float iy00 = -u0*sn + v0*cs, iy01 = -u0*sn + v1*cs;
    float iy10 = -u1*sn + v0*cs, iy11 = -u1*sn + v1*cs;
    int x_base = (int)floorf(fminf(fminf(ix00, ix01), fminf(ix10, ix11)) + cx) - 1;
    int y_base = (int)floorf(fminf(fminf(iy00, iy01), fminf(iy10, iy11)) + cx) - 1;

    // Stage the input tile; OOB cells get 0 (this IS the zero padding).
    const uint2* __restrict__ img = g_x1 + n * HW;
    int tid = threadIdx.x;
    #pragma unroll
    for (int k = 0; k < (IN_DIM * IN_DIM) / TPB; k++) {
        int c = tid + k * TPB;
        int row = c / IN_DIM;
        int col = c - row * IN_DIM;
        int gy = y_base + row;
        int gx = x_base + col;
        uint2 val = make_uint2(0u, 0u);
        if ((unsigned)gy < HH && (unsigned)gx < WW)
            val = __ldg(img + gy * WW + gx);
        tile[row * PITCH + col] = val;
    }
    __syncthreads();

    // R8 lane map: tid&7 = quad in x, tid>>3 = row.
    int qx = tid & 7;
    int yy = tid >> 3;                         // 0..31
    int w = tx + qx * 4;
    int h = ty + yy;

    float u = (float)w - cx;
    float v = (float)h - cx;
    // Local (tile) sample coordinates; advance by (cs, -sn) per pixel.
    float jx =  u * cs + v * sn + cx - (float)x_base;
    float jy = -u * sn + v * cs + cx - (float)y_base;

    float res[12];
    #pragma unroll
    for (int p = 0; p < 4; p++) {
        float x0f = floorf(jx), y0f = floorf(jy);
        int   lx  = (int)x0f,   ly  = (int)y0f;
        float fx = jx - x0f, fy = jy - y0f;

        float w00 = (1.f - fy) * (1.f - fx);
        float w01 = (1.f - fy) * fx;
        float w10 = fy * (1.f - fx);
        float w11 = fy * fx;

        const uint2* row0 = tile + ly * PITCH + lx;
        uint2 r00 = row0[0];
        uint2 r01 = row0[1];
        uint2 r10 = row0[PITCH];
        uint2 r11 = row0[PITCH + 1];

        float2 a00 = __half22float2(*(__half2*)&r00.x);
        float2 a01 = __half22float2(*(__half2*)&r01.x);
        float2 a10 = __half22float2(*(__half2*)&r10.x);
        float2 a11 = __half22float2(*(__half2*)&r11.x);
        float  c00 = __low2float(*(__half2*)&r00.y);
        float  c01 = __low2float(*(__half2*)&r01.y);
        float  c10 = __low2float(*(__half2*)&r10.y);
        float  c11 = __low2float(*(__half2*)&r11.y);

        res[p*3 + 0] = w00*a00.x + w01*a01.x + w10*a10.x + w11*a11.x;
        res[p*3 + 1] = w00*a00.y + w01*a01.y + w10*a10.y + w11*a11.y;
        res[p*3 + 2] = w00*c00   + w01*c01   + w10*c10   + w11*c11;

        jx += cs;
        jy -= sn;
    }

    float4* o = (float4*)(out + ((size_t)m * HW + (size_t)h * WW + w) * 3);
    o[0] = make_float4(res[0], res[1], res[2],  res[3]);
    o[1] = make_float4(res[4], res[5], res[6],  res[7]);
    o[2] = make_float4(res[8], res[9], res[10], res[11]);
}

extern "C" void kernel_launch(void* const* d_in, const int* in_sizes, int n_in,
                              void* d_out, int out_size)
{
    (void)in_sizes; (void)n_in; (void)out_size;
    const float* xs = (const float*)d_in[0];
    float* out = (float*)d_out;

    dim3 blk(256);
    dim3 g1((HW + 255) / 256, SS * BB);                     // (196, 84)
    dim3 g2((WW / TILE) * (HH / TILE), RR * SS * BB);       // (49, 420)

    stage1_shift<<<g1, blk>>>(xs);
    stage2_rotate<<<g2, blk>>>(out);
}

// round 14
// speedup vs baseline: 1.0393x; 1.0393x over previous
#include <cuda_runtime.h>
#include <cuda_fp16.h>

#define HH 224
#define WW 224
#define BB 4
#define SS 21
#define RR 5
#define HW (HH*WW)

#define TILE 32
#define TPB 256
#define IN_DIM 48
#define PITCH 49          // 48 + 1 pad (8B entries): spreads banks across rows

// Stage-1 intermediate: 84 shifted images, HWC pixels packed as half4 (8 B).
__device__ uint2 g_x1[SS * BB * HW];    // 33.7 MB

// cos/sin of ANGLES = {-0.5236, -0.2618, 0, 0.2618, 0.5236} (float64-accurate)
__constant__ float c_cos[RR] = {0.86602479158f, 0.96592566784f, 1.0f,
                                0.96592566784f, 0.86602479158f};
__constant__ float c_sin[RR] = {-0.50000106036f, -0.25881963644f, 0.0f,
                                 0.25881963644f,  0.50000106036f};

// ---------------------------------------------------------------------------
// Stage 1: axis-aligned shifts are exactly 2-tap (frac is 0 or 0.5, one axis).
// One thread = one pixel. Writes 8B half4.
// ---------------------------------------------------------------------------
__global__ void __launch_bounds__(256) stage1_shift(const float* __restrict__ xs)
{
    int idx = blockIdx.x * 256 + threadIdx.x;
    if (idx >= HW) return;
    int n = blockIdx.y;          // 0..83 = s*B + b
    int s = n >> 2;
    int b = n & 3;
    int h = idx / WW;
    int w = idx - h * WW;

    // Shift order: up p=1..5 (+y), down p=1..5 (-y), left (+x), right (-x),
    // plus identity. Normalized p/(W-1) -> p/2 pixels.
    int axis;                    // 0 = shift along y, 1 = along x
    float delta;
    if      (s < 5)  { axis = 0; delta =  (float)(s + 1)  * 0.5f; }
    else if (s < 10) { axis = 0; delta = -(float)(s - 4)  * 0.5f; }
    else if (s < 15) { axis = 1; delta =  (float)(s - 9)  * 0.5f; }
    else if (s < 20) { axis = 1; delta = -(float)(s - 14) * 0.5f; }
    else             { axis = 0; delta = 0.f; }

    float coord = (axis == 0 ? (float)h : (float)w) + delta;
    float i0f = floorf(coord);
    int   i0  = (int)i0f;
    float f   = coord - i0f;     // 0 or 0.5

    const float* img = xs + b * (HW * 3);
    float ax = 0.f, ay = 0.f, az = 0.f;
    #pragma unroll
    for (int j = 0; j < 2; j++) {
        int i = i0 + j;
        float wt = j ? f : (1.f - f);
        int y = axis == 0 ? i : h;
        int x = axis == 0 ? w : i;
        if (wt != 0.f && (unsigned)y < HH && (unsigned)x < WW) {
            const float* p = img + (y * WW + x) * 3;
            ax += wt * p[0];
            ay += wt * p[1];
            az += wt * p[2];
        }
    }
    __half2 lo = __floats2half2_rn(ax, ay);
    __half2 hi = __floats2half2_rn(az, 0.f);
    uint2 v;
    v.x = *(unsigned*)&lo;
    v.y = *(unsigned*)&hi;
    g_x1[n * HW + idx] = v;
}

// ---------------------------------------------------------------------------
// Stage 2: rotation sampling, smem-tiled (R8 layout: 8B cells, 4x LDS.64).
// Out-of-image cells are ZERO-filled in the tile, which implements the
// zero-padding exactly: the inner loop has NO boundary logic at all.
// Every tap is provably inside the 48x48 tile (span <= 46).
// Thread = 4 horizontally-consecutive pixels -> 3 STG.128.
// ---------------------------------------------------------------------------
__global__ void __launch_bounds__(TPB) stage2_rotate(float* __restrict__ out)
{
    __shared__ uint2 tile[IN_DIM * PITCH];

    int m = blockIdx.y;                        // 0..419
    int r = m / (SS * BB);
    int n = m - r * (SS * BB);
    int tbx = blockIdx.x % (WW / TILE);
    int tby = blockIdx.x / (WW / TILE);
    int tx = tbx * TILE;
    int ty = tby * TILE;

    const float cx = 111.5f;
    float cs = c_cos[r], sn = c_sin[r];

    // Input bounding box of the tile (linear map -> extrema at corners).
    float u0 = (float)tx - cx,  u1 = (float)(tx + TILE - 1) - cx;
    float v0 = (float)ty - cx,  v1 = (float)(ty + TILE - 1) - cx;
    float ix00 = u0*cs + v0*sn, ix01 = u0*cs + v1*sn;
    float ix10 = u1*cs + v0*sn, ix11 = u1*cs + v1*sn;
    float iy00 = -u0*sn + v0*cs, iy01 = -u0*sn + v1*cs;
    float iy10 = -u1*sn + v0*cs, iy11 = -u1*sn + v1*cs;
    int x_base = (int)floorf(fminf(fminf(ix00, ix01), fminf(ix10, ix11)) + cx) - 1;
    int y_base = (int)floorf(fminf(fminf(iy00, iy01), fminf(iy10, iy11)) + cx) - 1;

    // Stage the input tile; OOB cells get 0 (this IS the zero padding).
    const uint2* __restrict__ img = g_x1 + n * HW;
    int tid = threadIdx.x;
    #pragma unroll
    for (int k = 0; k < (IN_DIM * IN_DIM) / TPB; k++) {
        int c = tid + k * TPB;
        int row = c / IN_DIM;
        int col = c - row * IN_DIM;
        int gy = y_base + row;
        int gx = x_base + col;
        uint2 val = make_uint2(0u, 0u);
        if ((unsigned)gy < HH && (unsigned)gx < WW)
            val = __ldg(img + gy * WW + gx);
        tile[row * PITCH + col] = val;
    }
    __syncthreads();

    // R8 lane map: tid&7 = quad in x, tid>>3 = row.
    int qx = tid & 7;
    int yy = tid >> 3;                         // 0..31
    int w = tx + qx * 4;
    int h = ty + yy;

    float u = (float)w - cx;
    float v = (float)h - cx;
    // Local (tile) sample coordinates; advance by (cs, -sn) per pixel.
    float jx =  u * cs + v * sn + cx - (float)x_base;
    float jy = -u * sn + v * cs + cx - (float)y_base;

    float res[12];
    #pragma unroll
    for (int p = 0; p < 4; p++) {
        float x0f = floorf(jx), y0f = floorf(jy);
        int   lx  = (int)x0f,   ly  = (int)y0f;
        float fx = jx - x0f, fy = jy - y0f;

        float w00 = (1.f - fy) * (1.f - fx);
        float w01 = (1.f - fy) * fx;
        float w10 = fy * (1.f - fx);
        float w11 = fy * fx;

        const uint2* row0 = tile + ly * PITCH + lx;
        uint2 r00 = row0[0];
        uint2 r01 = row0[1];
        uint2 r10 = row0[PITCH];
        uint2 r11 = row0[PITCH + 1];

        float2 a00 = __half22float2(*(__half2*)&r00.x);
        float2 a01 = __half22float2(*(__half2*)&r01.x);
        float2 a10 = __half22float2(*(__half2*)&r10.x);
        float2 a11 = __half22float2(*(__half2*)&r11.x);
        float  c00 = __low2float(*(__half2*)&r00.y);
        float  c01 = __low2float(*(__half2*)&r01.y);
        float  c10 = __low2float(*(__half2*)&r10.y);
        float  c11 = __low2float(*(__half2*)&r11.y);

        res[p*3 + 0] = w00*a00.x + w01*a01.x + w10*a10.x + w11*a11.x;
        res[p*3 + 1] = w00*a00.y + w01*a01.y + w10*a10.y + w11*a11.y;
        res[p*3 + 2] = w00*c00   + w01*c01   + w10*c10   + w11*c11;

        jx += cs;
        jy -= sn;
    }

    float4* o = (float4*)(out + ((size_t)m * HW + (size_t)h * WW + w) * 3);
    o[0] = make_float4(res[0], res[1], res[2],  res[3]);
    o[1] = make_float4(res[4], res[5], res[6],  res[7]);
    o[2] = make_float4(res[8], res[9], res[10], res[11]);
}

extern "C" void kernel_launch(void* const* d_in, const int* in_sizes, int n_in,
                              void* d_out, int out_size)
{
    (void)in_sizes; (void)n_in; (void)out_size;
    const float* xs = (const float*)d_in[0];
    float* out = (float*)d_out;

    dim3 blk(256);
    dim3 g1((HW + 255) / 256, SS * BB);                     // (196, 84)
    dim3 g2((WW / TILE) * (HH / TILE), RR * SS * BB);       // (49, 420)

    stage1_shift<<<g1, blk>>>(xs);
    stage2_rotate<<<g2, blk>>>(out);
}

// round 15
// speedup vs baseline: 1.0405x; 1.0012x over previous
#include <cuda_runtime.h>
#include <cuda_fp16.h>

#define HH 224
#define WW 224
#define BB 4
#define SS 21
#define RR 5
#define HW (HH*WW)

#define TILE 32
#define TPB 256
#define IN_DIM 48
#define PITCH 49          // 48 + 1 pad (8B entries): spreads banks across rows

// Stage-1 intermediate: 84 shifted images, HWC pixels packed as half4 (8 B).
__device__ uint2 g_x1[SS * BB * HW];    // 33.7 MB

// cos/sin of ANGLES = {-0.5236, -0.2618, 0, 0.2618, 0.5236} (float64-accurate)
__constant__ float c_cos[RR] = {0.86602479158f, 0.96592566784f, 1.0f,
                                0.96592566784f, 0.86602479158f};
__constant__ float c_sin[RR] = {-0.50000106036f, -0.25881963644f, 0.0f,
                                 0.25881963644f,  0.50000106036f};

// ---------------------------------------------------------------------------
// Stage 1: axis-aligned shifts are exactly 2-tap (frac is 0 or 0.5, one axis).
// One thread = one pixel. Writes 8B half4.
// ---------------------------------------------------------------------------
__global__ void __launch_bounds__(256) stage1_shift(const float* __restrict__ xs)
{
    int idx = blockIdx.x * 256 + threadIdx.x;
    if (idx >= HW) return;
    int n = blockIdx.y;          // 0..83 = s*B + b
    int s = n >> 2;
    int b = n & 3;
    int h = idx / WW;
    int w = idx - h * WW;

    // Shift order: up p=1..5 (+y), down p=1..5 (-y), left (+x), right (-x),
    // plus identity. Normalized p/(W-1) -> p/2 pixels.
    int axis;                    // 0 = shift along y, 1 = along x
    float delta;
    if      (s < 5)  { axis = 0; delta =  (float)(s + 1)  * 0.5f; }
    else if (s < 10) { axis = 0; delta = -(float)(s - 4)  * 0.5f; }
    else if (s < 15) { axis = 1; delta =  (float)(s - 9)  * 0.5f; }
    else if (s < 20) { axis = 1; delta = -(float)(s - 14) * 0.5f; }
    else             { axis = 0; delta = 0.f; }

    float coord = (axis == 0 ? (float)h : (float)w) + delta;
    float i0f = floorf(coord);
    int   i0  = (int)i0f;
    float f   = coord - i0f;     // 0 or 0.5

    const float* img = xs + b * (HW * 3);
    float ax = 0.f, ay = 0.f, az = 0.f;
    #pragma unroll
    for (int j = 0; j < 2; j++) {
        int i = i0 + j;
        float wt = j ? f : (1.f - f);
        int y = axis == 0 ? i : h;
        int x = axis == 0 ? w : i;
        if (wt != 0.f && (unsigned)y < HH && (unsigned)x < WW) {
            const float* p = img + (y * WW + x) * 3;
            ax += wt * p[0];
            ay += wt * p[1];
            az += wt * p[2];
        }
    }
    __half2 lo = __floats2half2_rn(ax, ay);
    __half2 hi = __floats2half2_rn(az, 0.f);
    uint2 v;
    v.x = *(unsigned*)&lo;
    v.y = *(unsigned*)&hi;
    g_x1[n * HW + idx] = v;
}

// ---------------------------------------------------------------------------
// Stage 2: rotation sampling, smem-tiled (R8 layout: 8B cells, 4x LDS.64).
// Out-of-image cells are ZERO-filled in the tile, which implements the
// zero-padding exactly: the inner loop has NO boundary logic at all.
// Every tap is provably inside the 48x48 tile (span <= 46).
// Thread = 4 horizontally-consecutive pixels -> 3 STG.128.
// ---------------------------------------------------------------------------
__global__ void __launch_bounds__(TPB) stage2_rotate(float* __restrict__ out)
{
    __shared__ uint2 tile[IN_DIM * PITCH];

    int m = blockIdx.y;                        // 0..419
    int r = m / (SS * BB);
    int n = m - r * (SS * BB);
    int tbx = blockIdx.x % (WW / TILE);
    int tby = blockIdx.x / (WW / TILE);
    int tx = tbx * TILE;
    int ty = tby * TILE;

    const float cx = 111.5f;
    float cs = c_cos[r], sn = c_sin[r];

    // Input bounding box of the tile (linear map -> extrema at corners).
    float u0 = (float)tx - cx,  u1 = (float)(tx + TILE - 1) - cx;
    float v0 = (float)ty - cx,  v1 = (float)(ty + TILE - 1) - cx;
    float ix00 = u0*cs + v0*sn, ix01 = u0*cs + v1*sn;
    float ix10 = u1*cs + v0*sn, ix11 = u1*cs + v1*sn;
    float iy00 = -u0*sn + v0*cs, iy01 = -u0*sn + v1*cs;
    float iy10 = -u1*sn + v0*cs, iy11 = -u1*sn + v1*cs;
    int x_base = (int)floorf(fminf(fminf(ix00, ix01), fminf(ix10, ix11)) + cx) - 1;
    int y_base = (int)floorf(fminf(fminf(iy00, iy01), fminf(iy10, iy11)) + cx) - 1;

    // Stage the input tile; OOB cells get 0 (this IS the zero padding).
    const uint2* __restrict__ img = g_x1 + n * HW;
    int tid = threadIdx.x;
    #pragma unroll
    for (int k = 0; k < (IN_DIM * IN_DIM) / TPB; k++) {
        int c = tid + k * TPB;
        int row = c / IN_DIM;
        int col = c - row * IN_DIM;
        int gy = y_base + row;
        int gx = x_base + col;
        uint2 val = make_uint2(0u, 0u);
        if ((unsigned)gy < HH && (unsigned)gx < WW)
            val = __ldg(img + gy * WW + gx);
        tile[row * PITCH + col] = val;
    }
    __syncthreads();

    // R8 lane map: tid&7 = quad in x, tid>>3 = row.
    int qx = tid & 7;
    int yy = tid >> 3;                         // 0..31
    int w = tx + qx * 4;
    int h = ty + yy;

    float u = (float)w - cx;
    float v = (float)h - cx;
    // Local (tile) sample coordinates; advance by (cs, -sn) per pixel.
    float jx =  u * cs + v * sn + cx - (float)x_base;
    float jy = -u * sn + v * cs + cx - (float)y_base;

    float res[12];
    #pragma unroll
    for (int p = 0; p < 4; p++) {
        float x0f = floorf(jx), y0f = floorf(jy);
        int   lx  = (int)x0f,   ly  = (int)y0f;
        float fx = jx - x0f, fy = jy - y0f;

        float w00 = (1.f - fy) * (1.f - fx);
        float w01 = (1.f - fy) * fx;
        float w10 = fy * (1.f - fx);
        float w11 = fy * fx;

        const uint2* row0 = tile + ly * PITCH + lx;
        uint2 r00 = row0[0];
        uint2 r01 = row0[1];
        uint2 r10 = row0[PITCH];
        uint2 r11 = row0[PITCH + 1];

        float2 a00 = __half22float2(*(__half2*)&r00.x);
        float2 a01 = __half22float2(*(__half2*)&r01.x);
        float2 a10 = __half22float2(*(__half2*)&r10.x);
        float2 a11 = __half22float2(*(__half2*)&r11.x);
        float  c00 = __low2float(*(__half2*)&r00.y);
        float  c01 = __low2float(*(__half2*)&r01.y);
        float  c10 = __low2float(*(__half2*)&r10.y);
        float  c11 = __low2float(*(__half2*)&r11.y);

        res[p*3 + 0] = w00*a00.x + w01*a01.x + w10*a10.x + w11*a11.x;
        res[p*3 + 1] = w00*a00.y + w01*a01.y + w10*a10.y + w11*a11.y;
        res[p*3 + 2] = w00*c00   + w01*c01   + w10*c10   + w11*c11;

        jx += cs;
        jy -= sn;
    }

    float4* o = (float4*)(out + ((size_t)m * HW + (size_t)h * WW + w) * 3);
    o[0] = make_float4(res[0], res[1], res[2],  res[3]);
    o[1] = make_float4(res[4], res[5], res[6],  res[7]);
    o[2] = make_float4(res[8], res[9], res[10], res[11]);
}

extern "C" void kernel_launch(void* const* d_in, const int* in_sizes, int n_in,
                              void* d_out, int out_size)
{
    (void)in_sizes; (void)n_in; (void)out_size;
    const float* xs = (const float*)d_in[0];
    float* out = (float*)d_out;

    dim3 blk(256);
    dim3 g1((HW + 255) / 256, SS * BB);                     // (196, 84)
    dim3 g2((WW / TILE) * (HH / TILE), RR * SS * BB);       // (49, 420)

    stage1_shift<<<g1, blk>>>(xs);
    stage2_rotate<<<g2, blk>>>(out);
}